// round 1
// baseline (speedup 1.0000x reference)
#include <cuda_runtime.h>
#include <math.h>

#define NEXP 8
#define MAXB 4096

// ---------------- device scratch (no allocation allowed) ----------------
__device__ float g_w1f[NEXP * 32 * 27];        // folded conv1 weights
__device__ float g_b1f[NEXP * 32];
__device__ float g_w2f[NEXP * 64 * 32 * 9];    // folded conv2 weights
__device__ float g_b2f[NEXP * 64];
__device__ int   g_assign[MAXB * 2];
__device__ float g_gateval[MAXB * 2];
__device__ float g_importance[NEXP];
__device__ float g_loadcnt[NEXP];
__device__ float g_combined[MAXB * 10];

// ---------------- init: zero accumulators every launch (graph-safe) ----
__global__ void init_kernel(int n) {
    int i = blockIdx.x * blockDim.x + threadIdx.x;
    if (i < n) g_combined[i] = 0.f;
    if (i < NEXP) { g_importance[i] = 0.f; g_loadcnt[i] = 0.f; }
}

// ---------------- fold BN into conv weights ----------------------------
__global__ void fold_kernel(const float* __restrict__ w1, const float* __restrict__ b1,
                            const float* __restrict__ g1, const float* __restrict__ be1,
                            const float* __restrict__ rm1, const float* __restrict__ rv1,
                            const float* __restrict__ w2, const float* __restrict__ b2,
                            const float* __restrict__ g2, const float* __restrict__ be2,
                            const float* __restrict__ rm2, const float* __restrict__ rv2) {
    int i = blockIdx.x * blockDim.x + threadIdx.x;
    if (i < NEXP * 64 * 288) {                       // conv2 weights
        int eo = i / 288;                            // e*64+o
        float sc = g2[eo] / sqrtf(rv2[eo] + 1e-5f);
        g_w2f[i] = w2[i] * sc;
    }
    if (i < NEXP * 64) {
        float sc = g2[i] / sqrtf(rv2[i] + 1e-5f);
        g_b2f[i] = (b2[i] - rm2[i]) * sc + be2[i];
    }
    if (i < NEXP * 32 * 27) {                        // conv1 weights
        int eo = i / 27;
        float sc = g1[eo] / sqrtf(rv1[eo] + 1e-5f);
        g_w1f[i] = w1[i] * sc;
    }
    if (i < NEXP * 32) {
        float sc = g1[i] / sqrtf(rv1[i] + 1e-5f);
        g_b1f[i] = (b1[i] - rm1[i]) * sc + be1[i];
    }
}

// ---------------- gating: logits, top-2, gates, importance/load --------
__global__ void gate_kernel(const float* __restrict__ x, const float* __restrict__ wg) {
    int b = blockIdx.x;
    int t = threadIdx.x;
    __shared__ float s_part[8][NEXP];
    __shared__ float s_logit[NEXP];

    float acc[NEXP];
#pragma unroll
    for (int e2 = 0; e2 < NEXP; e2++) acc[e2] = 0.f;

    const float* xr = x + (size_t)b * 3072;
    for (int j = t; j < 3072; j += 256) {
        float xv = xr[j];
        const float4* w4 = reinterpret_cast<const float4*>(wg + (size_t)j * NEXP);
        float4 a = w4[0], c = w4[1];
        acc[0] += xv * a.x; acc[1] += xv * a.y; acc[2] += xv * a.z; acc[3] += xv * a.w;
        acc[4] += xv * c.x; acc[5] += xv * c.y; acc[6] += xv * c.z; acc[7] += xv * c.w;
    }
#pragma unroll
    for (int e2 = 0; e2 < NEXP; e2++)
        for (int off = 16; off; off >>= 1)
            acc[e2] += __shfl_down_sync(0xffffffffu, acc[e2], off);

    int warp = t >> 5, lane = t & 31;
    if (lane == 0) {
#pragma unroll
        for (int e2 = 0; e2 < NEXP; e2++) s_part[warp][e2] = acc[e2];
    }
    __syncthreads();
    if (t < NEXP) {
        float v = 0.f;
#pragma unroll
        for (int w = 0; w < 8; w++) v += s_part[w][t];
        s_logit[t] = v;
    }
    __syncthreads();
    if (t == 0) {
        float v1 = -INFINITY, v2 = -INFINITY;
        int i1 = 0, i2 = 0;
#pragma unroll
        for (int e2 = 0; e2 < NEXP; e2++) {
            float v = s_logit[e2];
            if (v > v1)      { v2 = v1; i2 = i1; v1 = v; i1 = e2; }
            else if (v > v2) { v2 = v;  i2 = e2; }
        }
        float ex = expf(v2 - v1);           // <= 1, stable softmax over top-2
        float denom = 1.f + ex;
        float gg1 = 1.f / denom;
        float gg2 = ex / denom;
        g_assign[2 * b]     = i1;
        g_assign[2 * b + 1] = i2;
        g_gateval[2 * b]     = gg1;
        g_gateval[2 * b + 1] = gg2;
        atomicAdd(&g_importance[i1], gg1);
        atomicAdd(&g_importance[i2], gg2);
        atomicAdd(&g_loadcnt[i1], 1.f);
        if (gg2 > 0.f) atomicAdd(&g_loadcnt[i2], 1.f);
    }
}

// ---------------- loss ---------------------------------------------------
__global__ void loss_kernel(float* __restrict__ out) {
    float mi = 0.f, ml = 0.f;
#pragma unroll
    for (int e2 = 0; e2 < NEXP; e2++) { mi += g_importance[e2]; ml += g_loadcnt[e2]; }
    mi *= (1.f / NEXP); ml *= (1.f / NEXP);
    float vi = 0.f, vl = 0.f;
#pragma unroll
    for (int e2 = 0; e2 < NEXP; e2++) {
        float d1 = g_importance[e2] - mi; vi += d1 * d1;
        float d2 = g_loadcnt[e2]   - ml; vl += d2 * d2;
    }
    vi *= (1.f / (NEXP - 1)); vl *= (1.f / (NEXP - 1));
    out[0] = 0.01f * (vi / (mi * mi + 1e-10f) + vl / (ml * ml + 1e-10f));
}

// ---------------- expert forward: one block per (sample, slot) pair ----
// SMEM layout (floats):
//   s_p1  [32][18][19]  = 10944   padded pooled1 (row stride 19 vs bank conflicts)
//   s_p2  [4096]        =  4096   pooled2 flat (matches reshape order c*64+ph*8+pw)
//   sA                  =  9248   union: stage1 {xpad 3468, w1 864, b1 32} / stage2 {w2 9216, b2 32}
// total = 24288 floats = 97152 bytes -> 2 blocks/SM
#define SMEM_FLOATS 24288

__global__ void __launch_bounds__(256, 2)
expert_kernel(const float* __restrict__ x, const float* __restrict__ fc_w,
              const float* __restrict__ fc_b) {
    extern __shared__ float sm[];
    float* s_p1 = sm;               // 10944
    float* s_p2 = sm + 10944;       // 4096
    float* sA   = sm + 15040;       // 9248

    int t = threadIdx.x;
    int p = blockIdx.x;
    int b = p >> 1;
    int e = g_assign[p];
    float gate = g_gateval[p];

    // ---- stage 1: load x (zero-padded) + folded conv1 weights ----
    float* s_x  = sA;               // 3*34*34 = 3468
    float* s_w1 = sA + 3468;        // 864
    float* s_b1 = sA + 4332;        // 32

    for (int i = t; i < 10944; i += 256) s_p1[i] = 0.f;
    const float* xr = x + (size_t)b * 3072;
    for (int i = t; i < 3468; i += 256) {
        int c = i / 1156, rem = i % 1156, r = rem / 34, cc = rem % 34;
        float v = 0.f;
        if (r >= 1 && r <= 32 && cc >= 1 && cc <= 32)
            v = xr[c * 1024 + (r - 1) * 32 + (cc - 1)];
        s_x[i] = v;
    }
    for (int i = t; i < 864; i += 256) s_w1[i] = g_w1f[e * 864 + i];
    if (t < 32) s_b1[t] = g_b1f[e * 32 + t];
    __syncthreads();

    // ---- conv1 + bias + relu + 2x2 maxpool -> s_p1 interior ----
    // item = (co_group of 8, ph, pw): 4 groups * 256 pooled positions = 1024 items
    for (int it = 0; it < 4; it++) {
        int item = t + (it << 8);
        int cg = item >> 8;
        int sp = item & 255;
        int ph = sp >> 4, pw = sp & 15;
        float a0[8], a1[8], a2[8], a3[8];
#pragma unroll
        for (int j = 0; j < 8; j++) { a0[j] = a1[j] = a2[j] = a3[j] = 0.f; }
        int y0 = 2 * ph, x0 = 2 * pw;
#pragma unroll
        for (int ci = 0; ci < 3; ci++)
#pragma unroll
            for (int kh = 0; kh < 3; kh++)
#pragma unroll
                for (int kw = 0; kw < 3; kw++) {
                    const float* xp = &s_x[ci * 1156 + (y0 + kh) * 34 + (x0 + kw)];
                    float v00 = xp[0],  v01 = xp[1];
                    float v10 = xp[34], v11 = xp[35];
                    int wo = ci * 9 + kh * 3 + kw;
#pragma unroll
                    for (int j = 0; j < 8; j++) {
                        float w = s_w1[(cg * 8 + j) * 27 + wo];
                        a0[j] += w * v00; a1[j] += w * v01;
                        a2[j] += w * v10; a3[j] += w * v11;
                    }
                }
#pragma unroll
        for (int j = 0; j < 8; j++) {
            int co = cg * 8 + j;
            float m = fmaxf(fmaxf(a0[j], a1[j]), fmaxf(a2[j], a3[j]));
            m = fmaxf(m + s_b1[co], 0.f);
            s_p1[co * 342 + (ph + 1) * 19 + (pw + 1)] = m;   // 342 = 18*19
        }
    }
    __syncthreads();

    // ---- conv2 + bias + relu + 2x2 maxpool -> s_p2, in 2 chunks of 32 oc ----
    float* s_w2 = sA;          // 9216
    float* s_b2 = sA + 9216;   // 32
    for (int chunk = 0; chunk < 2; chunk++) {
        for (int i = t; i < 9216; i += 256)
            s_w2[i] = g_w2f[e * 18432 + chunk * 9216 + i];
        if (t < 32) s_b2[t] = g_b2f[e * 64 + chunk * 32 + t];
        __syncthreads();

        int cog = t >> 6;            // 4 groups of 8 oc
        int sp = t & 63;
        int ph = sp >> 3, pw = sp & 7;
        float a0[8], a1[8], a2[8], a3[8];
#pragma unroll
        for (int j = 0; j < 8; j++) { a0[j] = a1[j] = a2[j] = a3[j] = 0.f; }
        int y0 = 2 * ph, x0 = 2 * pw;
        for (int ci = 0; ci < 32; ci++) {
            const float* pb = &s_p1[ci * 342];
            const float* wb = &s_w2[(cog * 8) * 288 + ci * 9];
#pragma unroll
            for (int kh = 0; kh < 3; kh++)
#pragma unroll
                for (int kw = 0; kw < 3; kw++) {
                    const float* pp = pb + (y0 + kh) * 19 + (x0 + kw);
                    float v00 = pp[0],  v01 = pp[1];
                    float v10 = pp[19], v11 = pp[20];
                    int wo = kh * 3 + kw;
#pragma unroll
                    for (int j = 0; j < 8; j++) {
                        float w = wb[j * 288 + wo];   // warp-uniform -> broadcast
                        a0[j] += w * v00; a1[j] += w * v01;
                        a2[j] += w * v10; a3[j] += w * v11;
                    }
                }
        }
#pragma unroll
        for (int j = 0; j < 8; j++) {
            int col = cog * 8 + j;
            float m = fmaxf(fmaxf(a0[j], a1[j]), fmaxf(a2[j], a3[j]));
            m = fmaxf(m + s_b2[col], 0.f);
            int co = chunk * 32 + col;
            s_p2[co * 64 + ph * 8 + pw] = m;
        }
        __syncthreads();
    }

    // ---- fc (4096 -> 10) + gate * exp -> atomic combine ----
    __shared__ float s_out[10];
    if (t < 10) s_out[t] = 0.f;
    float facc[10];
#pragma unroll
    for (int o = 0; o < 10; o++) facc[o] = 0.f;
    const float* fw = fc_w + (size_t)e * 40960;
    for (int j = t; j < 4096; j += 256) {
        float v = s_p2[j];
#pragma unroll
        for (int o = 0; o < 10; o++) facc[o] += v * fw[o * 4096 + j];
    }
    __syncthreads();
#pragma unroll
    for (int o = 0; o < 10; o++) {
        float v = facc[o];
        for (int off = 16; off; off >>= 1) v += __shfl_down_sync(0xffffffffu, v, off);
        if ((t & 31) == 0) atomicAdd(&s_out[o], v);
    }
    __syncthreads();
    if (t < 10) {
        float outv = s_out[t] + fc_b[e * 10 + t];
        atomicAdd(&g_combined[b * 10 + t], gate * expf(outv));
    }
}

// ---------------- finalize: y = log(combined, eps where 0) --------------
__global__ void final_kernel(float* __restrict__ out, int n) {
    int i = blockIdx.x * blockDim.x + threadIdx.x;
    if (i < n) {
        float c = g_combined[i];
        if (c == 0.f) c = 2.220446049250313e-16f;
        out[i] = logf(c);
    }
}

// ---------------- launch --------------------------------------------------
extern "C" void kernel_launch(void* const* d_in, const int* in_sizes, int n_in,
                              void* d_out, int out_size) {
    const float* x      = (const float*)d_in[0];
    // d_in[1] = index (unused by the math)
    const float* w_gate = (const float*)d_in[2];
    const float* w1  = (const float*)d_in[3];
    const float* b1  = (const float*)d_in[4];
    const float* g1  = (const float*)d_in[5];
    const float* be1 = (const float*)d_in[6];
    const float* rm1 = (const float*)d_in[7];
    const float* rv1 = (const float*)d_in[8];
    const float* w2  = (const float*)d_in[9];
    const float* b2  = (const float*)d_in[10];
    const float* g2  = (const float*)d_in[11];
    const float* be2 = (const float*)d_in[12];
    const float* rm2 = (const float*)d_in[13];
    const float* rv2 = (const float*)d_in[14];
    const float* fc_w = (const float*)d_in[15];
    const float* fc_b = (const float*)d_in[16];
    float* out = (float*)d_out;

    int B = in_sizes[0] / 3072;
    if (B > MAXB) B = MAXB;

    cudaFuncSetAttribute(expert_kernel,
                         cudaFuncAttributeMaxDynamicSharedMemorySize,
                         SMEM_FLOATS * 4);

    init_kernel<<<(B * 10 + 255) / 256, 256>>>(B * 10);
    fold_kernel<<<(NEXP * 64 * 288 + 255) / 256, 256>>>(
        w1, b1, g1, be1, rm1, rv1, w2, b2, g2, be2, rm2, rv2);
    gate_kernel<<<B, 256>>>(x, w_gate);
    loss_kernel<<<1, 1>>>(out + (out_size - 1));
    expert_kernel<<<B * 2, 256, SMEM_FLOATS * 4>>>(x, fc_w, fc_b);
    final_kernel<<<(B * 10 + 255) / 256, 256>>>(out, B * 10);
}

// round 4
// speedup vs baseline: 1.3678x; 1.3678x over previous
#include <cuda_runtime.h>
#include <math.h>

#define NEXP 8
#define MAXB 4096

typedef unsigned long long ull;

__device__ __forceinline__ ull dup2(float v) {
    ull r; asm("mov.b64 %0, {%1, %1};" : "=l"(r) : "f"(v)); return r;
}
__device__ __forceinline__ void fma2(ull& d, ull a, ull b) {
    asm("fma.rn.f32x2 %0, %1, %2, %0;" : "+l"(d) : "l"(a), "l"(b));
}
__device__ __forceinline__ float2 unpk(ull v) {
    float2 f; asm("mov.b64 {%0, %1}, %2;" : "=f"(f.x), "=f"(f.y) : "l"(v)); return f;
}

// ---------------- device scratch (no allocation allowed) ----------------
__device__ __align__(16) float g_w1t[NEXP * 27 * 32];  // folded conv1 w, [e][ci*9+wo][oc]
__device__ float g_b1f[NEXP * 32];
__device__ __align__(16) float g_w2t[NEXP * 2 * 32 * 9 * 32]; // [e][chunk][ci][wo][ocl]
__device__ float g_b2f[NEXP * 64];
__device__ int   g_assign[MAXB * 2];
__device__ float g_gateval[MAXB * 2];
__device__ float g_importance[NEXP];
__device__ float g_loadcnt[NEXP];
__device__ float g_combined[MAXB * 10];

// ---------------- init: zero accumulators every launch (graph-safe) ----
__global__ void init_kernel(int n) {
    int i = blockIdx.x * blockDim.x + threadIdx.x;
    if (i < n) g_combined[i] = 0.f;
    if (i < NEXP) { g_importance[i] = 0.f; g_loadcnt[i] = 0.f; }
}

// ---------------- fold BN into conv weights (transposed layouts) -------
__global__ void fold_kernel(const float* __restrict__ w1, const float* __restrict__ b1,
                            const float* __restrict__ g1, const float* __restrict__ be1,
                            const float* __restrict__ rm1, const float* __restrict__ rv1,
                            const float* __restrict__ w2, const float* __restrict__ b2,
                            const float* __restrict__ g2, const float* __restrict__ be2,
                            const float* __restrict__ rm2, const float* __restrict__ rv2) {
    int i = blockIdx.x * blockDim.x + threadIdx.x;
    if (i < NEXP * 18432) {                      // conv2 transposed
        int e = i / 18432, r = i % 18432;
        int chunk = r / 9216, r2 = r % 9216;
        int ciwo = r2 / 32, ocl = r2 % 32;
        int ci = ciwo / 9, wo = ciwo % 9;
        int oc = chunk * 32 + ocl;
        int eo = e * 64 + oc;
        float sc = g2[eo] / sqrtf(rv2[eo] + 1e-5f);
        g_w2t[i] = w2[e * 18432 + oc * 288 + ci * 9 + wo] * sc;
    }
    if (i < NEXP * 64) {
        float sc = g2[i] / sqrtf(rv2[i] + 1e-5f);
        g_b2f[i] = (b2[i] - rm2[i]) * sc + be2[i];
    }
    if (i < NEXP * 864) {                        // conv1 transposed
        int e = i / 864, r = i % 864;
        int ciwo = r / 32, ocl = r % 32;
        int ci = ciwo / 9, wo = ciwo % 9;
        int eo = e * 32 + ocl;
        float sc = g1[eo] / sqrtf(rv1[eo] + 1e-5f);
        g_w1t[i] = w1[e * 864 + ocl * 27 + ci * 9 + wo] * sc;
    }
    if (i < NEXP * 32) {
        float sc = g1[i] / sqrtf(rv1[i] + 1e-5f);
        g_b1f[i] = (b1[i] - rm1[i]) * sc + be1[i];
    }
}

// ---------------- gating: logits, top-2, gates, importance/load --------
__global__ void gate_kernel(const float* __restrict__ x, const float* __restrict__ wg) {
    int b = blockIdx.x;
    int t = threadIdx.x;
    __shared__ float s_part[8][NEXP];
    __shared__ float s_logit[NEXP];

    float acc[NEXP];
#pragma unroll
    for (int e2 = 0; e2 < NEXP; e2++) acc[e2] = 0.f;

    const float* xr = x + (size_t)b * 3072;
    for (int j = t; j < 3072; j += 256) {
        float xv = xr[j];
        const float4* w4 = reinterpret_cast<const float4*>(wg + (size_t)j * NEXP);
        float4 a = w4[0], c = w4[1];
        acc[0] += xv * a.x; acc[1] += xv * a.y; acc[2] += xv * a.z; acc[3] += xv * a.w;
        acc[4] += xv * c.x; acc[5] += xv * c.y; acc[6] += xv * c.z; acc[7] += xv * c.w;
    }
#pragma unroll
    for (int e2 = 0; e2 < NEXP; e2++)
        for (int off = 16; off; off >>= 1)
            acc[e2] += __shfl_down_sync(0xffffffffu, acc[e2], off);

    int warp = t >> 5, lane = t & 31;
    if (lane == 0) {
#pragma unroll
        for (int e2 = 0; e2 < NEXP; e2++) s_part[warp][e2] = acc[e2];
    }
    __syncthreads();
    if (t < NEXP) {
        float v = 0.f;
#pragma unroll
        for (int w = 0; w < 8; w++) v += s_part[w][t];
        s_logit[t] = v;
    }
    __syncthreads();
    if (t == 0) {
        float v1 = -INFINITY, v2 = -INFINITY;
        int i1 = 0, i2 = 0;
#pragma unroll
        for (int e2 = 0; e2 < NEXP; e2++) {
            float v = s_logit[e2];
            if (v > v1)      { v2 = v1; i2 = i1; v1 = v; i1 = e2; }
            else if (v > v2) { v2 = v;  i2 = e2; }
        }
        float ex = expf(v2 - v1);           // <= 1, stable softmax over top-2
        float denom = 1.f + ex;
        float gg1 = 1.f / denom;
        float gg2 = ex / denom;
        g_assign[2 * b]     = i1;
        g_assign[2 * b + 1] = i2;
        g_gateval[2 * b]     = gg1;
        g_gateval[2 * b + 1] = gg2;
        atomicAdd(&g_importance[i1], gg1);
        atomicAdd(&g_importance[i2], gg2);
        atomicAdd(&g_loadcnt[i1], 1.f);
        if (gg2 > 0.f) atomicAdd(&g_loadcnt[i2], 1.f);
    }
}

// ---------------- loss ---------------------------------------------------
__global__ void loss_kernel(float* __restrict__ out) {
    float mi = 0.f, ml = 0.f;
#pragma unroll
    for (int e2 = 0; e2 < NEXP; e2++) { mi += g_importance[e2]; ml += g_loadcnt[e2]; }
    mi *= (1.f / NEXP); ml *= (1.f / NEXP);
    float vi = 0.f, vl = 0.f;
#pragma unroll
    for (int e2 = 0; e2 < NEXP; e2++) {
        float d1 = g_importance[e2] - mi; vi += d1 * d1;
        float d2 = g_loadcnt[e2]   - ml; vl += d2 * d2;
    }
    vi *= (1.f / (NEXP - 1)); vl *= (1.f / (NEXP - 1));
    out[0] = 0.01f * (vi / (mi * mi + 1e-10f) + vl / (ml * ml + 1e-10f));
}

// ---------------- expert forward: one block per (sample, slot) pair ----
// SMEM layout (floats):
//   s_p1  [32][18][19]  = 10944   padded pooled1
//   s_p2  [4096]        =  4096   pooled2 flat (c*64+ph*8+pw)
//   sA                  =  9248   union:
//     stage1 {xpad 3*34*35=3570 (pad->3572 for 16B align), w1t 864, b1 32}
//     stage2 {w2t 9216, b2 32}
// total = 24288 floats = 97152 bytes -> 2 blocks/SM
#define SMEM_FLOATS 24288

__global__ void __launch_bounds__(256, 2)
expert_kernel(const float* __restrict__ x, const float* __restrict__ fc_w,
              const float* __restrict__ fc_b) {
    extern __shared__ float sm[];
    float* s_p1 = sm;               // 10944
    float* s_p2 = sm + 10944;       // 4096
    float* sA   = sm + 15040;       // 9248  (byte offset 60160, 16B aligned)

    int t = threadIdx.x;
    int p = blockIdx.x;
    int b = p >> 1;
    int e = g_assign[p];
    float gate = g_gateval[p];

    // ---- stage 1: load x (zero-padded, stride 35) + transposed conv1 w --
    float* s_x  = sA;               // uses 3570, padded to 3572 for alignment
    float* s_w1 = sA + 3572;        // 864  (byte offset 16B-aligned)
    float* s_b1 = sA + 4436;        // 32

    for (int i = t; i < 10944; i += 256) s_p1[i] = 0.f;
    const float* xr = x + (size_t)b * 3072;
    for (int i = t; i < 3570; i += 256) {
        int c = i / 1190, rem = i % 1190, r = rem / 35, cc = rem % 35;
        float v = 0.f;
        if (r >= 1 && r <= 32 && cc >= 1 && cc <= 32)
            v = xr[c * 1024 + (r - 1) * 32 + (cc - 1)];
        s_x[i] = v;
    }
    {
        const float4* src = reinterpret_cast<const float4*>(g_w1t + e * 864);
        float4* dst = reinterpret_cast<float4*>(s_w1);
        for (int i = t; i < 216; i += 256) dst[i] = src[i];
    }
    if (t < 32) s_b1[t] = g_b1f[e * 32 + t];
    __syncthreads();

    // ---- conv1 (FFMA2, oc-pairs) + relu + 2x2 maxpool -> s_p1 interior --
    // item: ocg (8 groups of 4 oc) x ph(16) x pq(8 pooled-col-pairs) = 1024
#pragma unroll 1
    for (int it = 0; it < 4; it++) {
        int item = t + (it << 8);
        int ocg = item >> 7;
        int pp = item & 127;
        int ph = pp >> 3, pq = pp & 7;
        int y0 = 2 * ph, x0 = 4 * pq;

        ull a0[2][4], a1[2][4];
#pragma unroll
        for (int r = 0; r < 2; r++)
#pragma unroll
            for (int c = 0; c < 4; c++) { a0[r][c] = 0ull; a1[r][c] = 0ull; }

#pragma unroll 1
        for (int ci = 0; ci < 3; ci++) {
            const float* wb = s_w1 + ci * 288 + ocg * 4;
            ull w0[9], w1r[9];
#pragma unroll
            for (int wo = 0; wo < 9; wo++) {
                w0[wo]  = *reinterpret_cast<const ull*>(wb + wo * 32);
                w1r[wo] = *reinterpret_cast<const ull*>(wb + wo * 32 + 2);
            }
            const float* xb = s_x + ci * 1190 + y0 * 35 + x0;
#pragma unroll
            for (int ir = 0; ir < 4; ir++) {
                ull xx[6];
#pragma unroll
                for (int dc = 0; dc < 6; dc++) xx[dc] = dup2(xb[ir * 35 + dc]);
#pragma unroll
                for (int r = 0; r < 2; r++) {
                    int kh = ir - r;
                    if (kh >= 0 && kh < 3) {
#pragma unroll
                        for (int kw = 0; kw < 3; kw++) {
#pragma unroll
                            for (int c = 0; c < 4; c++) {
                                fma2(a0[r][c], w0[kh * 3 + kw], xx[c + kw]);
                                fma2(a1[r][c], w1r[kh * 3 + kw], xx[c + kw]);
                            }
                        }
                    }
                }
            }
        }
        // pool 2x2 over (r, col pairs), bias+relu, store
        int oc = ocg * 4;
#pragma unroll
        for (int c2 = 0; c2 < 2; c2++) {
            float2 q00 = unpk(a0[0][2 * c2]), q01 = unpk(a0[0][2 * c2 + 1]);
            float2 q10 = unpk(a0[1][2 * c2]), q11 = unpk(a0[1][2 * c2 + 1]);
            float mlo = fmaxf(fmaxf(q00.x, q01.x), fmaxf(q10.x, q11.x));
            float mhi = fmaxf(fmaxf(q00.y, q01.y), fmaxf(q10.y, q11.y));
            int col = 2 * pq + c2 + 1;
            s_p1[oc * 342 + (ph + 1) * 19 + col]       = fmaxf(mlo + s_b1[oc], 0.f);
            s_p1[(oc + 1) * 342 + (ph + 1) * 19 + col] = fmaxf(mhi + s_b1[oc + 1], 0.f);
            float2 r00 = unpk(a1[0][2 * c2]), r01 = unpk(a1[0][2 * c2 + 1]);
            float2 r10 = unpk(a1[1][2 * c2]), r11 = unpk(a1[1][2 * c2 + 1]);
            float nlo = fmaxf(fmaxf(r00.x, r01.x), fmaxf(r10.x, r11.x));
            float nhi = fmaxf(fmaxf(r00.y, r01.y), fmaxf(r10.y, r11.y));
            s_p1[(oc + 2) * 342 + (ph + 1) * 19 + col] = fmaxf(nlo + s_b1[oc + 2], 0.f);
            s_p1[(oc + 3) * 342 + (ph + 1) * 19 + col] = fmaxf(nhi + s_b1[oc + 3], 0.f);
        }
    }
    __syncthreads();

    // ---- conv2 (FFMA2, oc-pairs) + relu + 2x2 maxpool -> s_p2 ----------
    float* s_w2 = sA;          // 9216 transposed [ci][wo][32]  (16B aligned)
    float* s_b2 = sA + 9216;   // 32
#pragma unroll 1
    for (int chunk = 0; chunk < 2; chunk++) {
        {
            const float4* src = reinterpret_cast<const float4*>(
                g_w2t + e * 18432 + chunk * 9216);
            float4* dst = reinterpret_cast<float4*>(s_w2);
            for (int i = t; i < 2304; i += 256) dst[i] = src[i];
        }
        if (t < 32) s_b2[t] = g_b2f[e * 64 + chunk * 32 + t];
        __syncthreads();

        int ocg = t >> 5;            // warp-uniform
        int sp = t & 31;
        int ph = sp >> 2, pq = sp & 3;
        int y0 = 2 * ph, x0 = 4 * pq;

        ull a0[2][4], a1[2][4];
#pragma unroll
        for (int r = 0; r < 2; r++)
#pragma unroll
            for (int c = 0; c < 4; c++) { a0[r][c] = 0ull; a1[r][c] = 0ull; }

#pragma unroll 1
        for (int ci = 0; ci < 32; ci++) {
            const float* wb = s_w2 + ci * 288 + ocg * 4;
            ull w0[9], w1r[9];
#pragma unroll
            for (int wo = 0; wo < 9; wo++) {
                w0[wo]  = *reinterpret_cast<const ull*>(wb + wo * 32);
                w1r[wo] = *reinterpret_cast<const ull*>(wb + wo * 32 + 2);
            }
            const float* xb = s_p1 + ci * 342 + y0 * 19 + x0;
#pragma unroll
            for (int ir = 0; ir < 4; ir++) {
                ull xx[6];
#pragma unroll
                for (int dc = 0; dc < 6; dc++) xx[dc] = dup2(xb[ir * 19 + dc]);
#pragma unroll
                for (int r = 0; r < 2; r++) {
                    int kh = ir - r;
                    if (kh >= 0 && kh < 3) {
#pragma unroll
                        for (int kw = 0; kw < 3; kw++) {
#pragma unroll
                            for (int c = 0; c < 4; c++) {
                                fma2(a0[r][c], w0[kh * 3 + kw], xx[c + kw]);
                                fma2(a1[r][c], w1r[kh * 3 + kw], xx[c + kw]);
                            }
                        }
                    }
                }
            }
        }
        int co = chunk * 32 + ocg * 4;
#pragma unroll
        for (int c2 = 0; c2 < 2; c2++) {
            float2 q00 = unpk(a0[0][2 * c2]), q01 = unpk(a0[0][2 * c2 + 1]);
            float2 q10 = unpk(a0[1][2 * c2]), q11 = unpk(a0[1][2 * c2 + 1]);
            float mlo = fmaxf(fmaxf(q00.x, q01.x), fmaxf(q10.x, q11.x));
            float mhi = fmaxf(fmaxf(q00.y, q01.y), fmaxf(q10.y, q11.y));
            int col = ph * 8 + 2 * pq + c2;
            s_p2[co * 64 + col]       = fmaxf(mlo + s_b2[ocg * 4], 0.f);
            s_p2[(co + 1) * 64 + col] = fmaxf(mhi + s_b2[ocg * 4 + 1], 0.f);
            float2 r00 = unpk(a1[0][2 * c2]), r01 = unpk(a1[0][2 * c2 + 1]);
            float2 r10 = unpk(a1[1][2 * c2]), r11 = unpk(a1[1][2 * c2 + 1]);
            float nlo = fmaxf(fmaxf(r00.x, r01.x), fmaxf(r10.x, r11.x));
            float nhi = fmaxf(fmaxf(r00.y, r01.y), fmaxf(r10.y, r11.y));
            s_p2[(co + 2) * 64 + col] = fmaxf(nlo + s_b2[ocg * 4 + 2], 0.f);
            s_p2[(co + 3) * 64 + col] = fmaxf(nhi + s_b2[ocg * 4 + 3], 0.f);
        }
        __syncthreads();
    }

    // ---- fc (4096 -> 10) + gate * exp -> atomic combine ----
    __shared__ float s_out[10];
    if (t < 10) s_out[t] = 0.f;
    float facc[10];
#pragma unroll
    for (int o = 0; o < 10; o++) facc[o] = 0.f;
    const float* fw = fc_w + (size_t)e * 40960;
    for (int j = t; j < 4096; j += 256) {
        float v = s_p2[j];
#pragma unroll
        for (int o = 0; o < 10; o++) facc[o] += v * fw[o * 4096 + j];
    }
    __syncthreads();
#pragma unroll
    for (int o = 0; o < 10; o++) {
        float v = facc[o];
        for (int off = 16; off; off >>= 1) v += __shfl_down_sync(0xffffffffu, v, off);
        if ((t & 31) == 0) atomicAdd(&s_out[o], v);
    }
    __syncthreads();
    if (t < 10) {
        float outv = s_out[t] + fc_b[e * 10 + t];
        atomicAdd(&g_combined[b * 10 + t], gate * expf(outv));
    }
}

// ---------------- finalize: y = log(combined, eps where 0) --------------
__global__ void final_kernel(float* __restrict__ out, int n) {
    int i = blockIdx.x * blockDim.x + threadIdx.x;
    if (i < n) {
        float c = g_combined[i];
        if (c == 0.f) c = 2.220446049250313e-16f;
        out[i] = logf(c);
    }
}

// ---------------- launch --------------------------------------------------
extern "C" void kernel_launch(void* const* d_in, const int* in_sizes, int n_in,
                              void* d_out, int out_size) {
    const float* x      = (const float*)d_in[0];
    // d_in[1] = index (unused by the math)
    const float* w_gate = (const float*)d_in[2];
    const float* w1  = (const float*)d_in[3];
    const float* b1  = (const float*)d_in[4];
    const float* g1  = (const float*)d_in[5];
    const float* be1 = (const float*)d_in[6];
    const float* rm1 = (const float*)d_in[7];
    const float* rv1 = (const float*)d_in[8];
    const float* w2  = (const float*)d_in[9];
    const float* b2  = (const float*)d_in[10];
    const float* g2  = (const float*)d_in[11];
    const float* be2 = (const float*)d_in[12];
    const float* rm2 = (const float*)d_in[13];
    const float* rv2 = (const float*)d_in[14];
    const float* fc_w = (const float*)d_in[15];
    const float* fc_b = (const float*)d_in[16];
    float* out = (float*)d_out;

    int B = in_sizes[0] / 3072;
    if (B > MAXB) B = MAXB;

    cudaFuncSetAttribute(expert_kernel,
                         cudaFuncAttributeMaxDynamicSharedMemorySize,
                         SMEM_FLOATS * 4);

    init_kernel<<<(B * 10 + 255) / 256, 256>>>(B * 10);
    fold_kernel<<<(NEXP * 18432 + 255) / 256, 256>>>(
        w1, b1, g1, be1, rm1, rv1, w2, b2, g2, be2, rm2, rv2);
    gate_kernel<<<B, 256>>>(x, w_gate);
    loss_kernel<<<1, 1>>>(out + (out_size - 1));
    expert_kernel<<<B * 2, 256, SMEM_FLOATS * 4>>>(x, fc_w, fc_b);
    final_kernel<<<(B * 10 + 255) / 256, 256>>>(out, B * 10);
}